// round 1
// baseline (speedup 1.0000x reference)
#include <cuda_runtime.h>
#include <math.h>

// Problem constants
#define M_TOK   8192      // B*S = 4*2048
#define D_IN    4096
#define Z_DIM   1024
#define D_OUT   4096
#define CAT_DIM 5120      // Z + D_IN
#define LN_EPS  1e-5f

// d_out packing: (out[8192,4096], mu[8192,1024], std[8192,1024])
#define OUT_OFF 0
#define MU_OFF  (M_TOK * (size_t)D_OUT)                  // 33554432
#define STD_OFF (MU_OFF + (size_t)M_TOK * Z_DIM)         // 41943040

// Scratch (device globals — allocation-free per harness rules)
__device__ float g_c[(size_t)M_TOK * Z_DIM];     // pre-LN buffer   (32 MB)
__device__ float g_h[(size_t)M_TOK * Z_DIM];     // post LN+tanh    (32 MB)
__device__ float g_cat[(size_t)M_TOK * CAT_DIM]; // tanh(concat)    (160 MB)

// ---------------------------------------------------------------------------
// GEMM: C[M,N] = A[M,K] * B[N,K]^T + bias[N]   (both A and B K-contiguous)
// mode 0: plain.  mode 1: C = exp(0.5*(acc+bias))  (std path)
// Tile 128x128x16, 256 threads, 8x8 per thread. All dims divide tiles.
// ---------------------------------------------------------------------------
#define BM 128
#define BN 128
#define BKK 16

__global__ void __launch_bounds__(256)
gemm_nt_kernel(const float* __restrict__ A, const float* __restrict__ B,
               const float* __restrict__ bias, float* __restrict__ C,
               int M, int N, int K, int mode)
{
    __shared__ float As[BKK][BM + 4];
    __shared__ float Bs[BKK][BN + 4];

    const int bm = blockIdx.y * BM;
    const int bn = blockIdx.x * BN;
    const int tid = threadIdx.x;
    const int tx = tid & 15;   // 0..15  -> N direction
    const int ty = tid >> 4;   // 0..15  -> M direction

    // global load mapping: 256 threads, each loads 2 rows x 4 floats
    const int lrow = tid >> 2;          // 0..63
    const int lcol = (tid & 3) * 4;     // 0,4,8,12

    const float* Aptr = A + (size_t)bm * K;
    const float* Bptr = B + (size_t)bn * K;

    float acc[8][8];
#pragma unroll
    for (int i = 0; i < 8; i++)
#pragma unroll
        for (int j = 0; j < 8; j++) acc[i][j] = 0.f;

    for (int k0 = 0; k0 < K; k0 += BKK) {
#pragma unroll
        for (int r = 0; r < 2; r++) {
            int row = lrow + r * 64;
            float4 v = *(const float4*)(Aptr + (size_t)row * K + k0 + lcol);
            As[lcol + 0][row] = v.x;
            As[lcol + 1][row] = v.y;
            As[lcol + 2][row] = v.z;
            As[lcol + 3][row] = v.w;
        }
#pragma unroll
        for (int r = 0; r < 2; r++) {
            int row = lrow + r * 64;
            float4 v = *(const float4*)(Bptr + (size_t)row * K + k0 + lcol);
            Bs[lcol + 0][row] = v.x;
            Bs[lcol + 1][row] = v.y;
            Bs[lcol + 2][row] = v.z;
            Bs[lcol + 3][row] = v.w;
        }
        __syncthreads();

#pragma unroll
        for (int k = 0; k < BKK; k++) {
            float a[8], b[8];
            *(float4*)(a)     = *(const float4*)&As[k][ty * 8];
            *(float4*)(a + 4) = *(const float4*)&As[k][ty * 8 + 4];
            *(float4*)(b)     = *(const float4*)&Bs[k][tx * 8];
            *(float4*)(b + 4) = *(const float4*)&Bs[k][tx * 8 + 4];
#pragma unroll
            for (int i = 0; i < 8; i++)
#pragma unroll
                for (int j = 0; j < 8; j++)
                    acc[i][j] = fmaf(a[i], b[j], acc[i][j]);
        }
        __syncthreads();
    }

    // epilogue
    float bv[8];
#pragma unroll
    for (int j = 0; j < 8; j++) bv[j] = bias[bn + tx * 8 + j];

#pragma unroll
    for (int i = 0; i < 8; i++) {
        size_t row = (size_t)(bm + ty * 8 + i);
        float* crow = C + row * N + bn + tx * 8;
#pragma unroll
        for (int j = 0; j < 8; j += 4) {
            float4 o;
            float v0 = acc[i][j + 0] + bv[j + 0];
            float v1 = acc[i][j + 1] + bv[j + 1];
            float v2 = acc[i][j + 2] + bv[j + 2];
            float v3 = acc[i][j + 3] + bv[j + 3];
            if (mode == 1) {
                v0 = expf(0.5f * v0); v1 = expf(0.5f * v1);
                v2 = expf(0.5f * v2); v3 = expf(0.5f * v3);
            }
            o.x = v0; o.y = v1; o.z = v2; o.w = v3;
            *(float4*)(crow + j) = o;
        }
    }
}

// ---------------------------------------------------------------------------
// LayerNorm (over 1024) + tanh. One block per row, 256 threads x 4 elems.
// ---------------------------------------------------------------------------
__global__ void __launch_bounds__(256)
ln_tanh_kernel(const float* __restrict__ in, const float* __restrict__ gamma,
               const float* __restrict__ beta, float* __restrict__ out)
{
    const int row = blockIdx.x;
    const int tid = threadIdx.x;
    const float* p = in + (size_t)row * Z_DIM;

    float4 v = *(const float4*)(p + tid * 4);

    __shared__ float red[8];
    // --- mean ---
    float s = v.x + v.y + v.z + v.w;
#pragma unroll
    for (int o = 16; o > 0; o >>= 1) s += __shfl_down_sync(0xffffffffu, s, o);
    if ((tid & 31) == 0) red[tid >> 5] = s;
    __syncthreads();
    float total;
    {
        float t = (tid < 8) ? red[tid] : 0.f;
#pragma unroll
        for (int o = 4; o > 0; o >>= 1) t += __shfl_down_sync(0xffu, t, o);
        if (tid == 0) red[0] = t;
    }
    __syncthreads();
    total = red[0];
    const float mean = total * (1.0f / Z_DIM);
    __syncthreads();

    // --- variance (two-pass) ---
    float d0 = v.x - mean, d1 = v.y - mean, d2 = v.z - mean, d3 = v.w - mean;
    float s2 = d0 * d0 + d1 * d1 + d2 * d2 + d3 * d3;
#pragma unroll
    for (int o = 16; o > 0; o >>= 1) s2 += __shfl_down_sync(0xffffffffu, s2, o);
    if ((tid & 31) == 0) red[tid >> 5] = s2;
    __syncthreads();
    {
        float t = (tid < 8) ? red[tid] : 0.f;
#pragma unroll
        for (int o = 4; o > 0; o >>= 1) t += __shfl_down_sync(0xffu, t, o);
        if (tid == 0) red[0] = t;
    }
    __syncthreads();
    const float var = red[0] * (1.0f / Z_DIM);
    const float rstd = rsqrtf(var + LN_EPS);

    const int col = tid * 4;
    float4 g = *(const float4*)(gamma + col);
    float4 b = *(const float4*)(beta + col);
    float4 o;
    o.x = tanhf(d0 * rstd * g.x + b.x);
    o.y = tanhf(d1 * rstd * g.y + b.y);
    o.z = tanhf(d2 * rstd * g.z + b.z);
    o.w = tanhf(d3 * rstd * g.w + b.w);
    *(float4*)(out + (size_t)row * Z_DIM + col) = o;
}

// ---------------------------------------------------------------------------
// Build tanh(concat(z, x)):  z = eps*std + mu (mu/std already in d_out)
// ---------------------------------------------------------------------------
__global__ void __launch_bounds__(256)
build_cat_kernel(const float* __restrict__ eps, const float* __restrict__ x,
                 const float* __restrict__ mu, const float* __restrict__ stdv,
                 float* __restrict__ cat)
{
    size_t idx = (size_t)blockIdx.x * blockDim.x + threadIdx.x;
    size_t total = (size_t)M_TOK * CAT_DIM;
    if (idx >= total) return;
    size_t row = idx / CAT_DIM;
    int col = (int)(idx - row * CAT_DIM);
    float val;
    if (col < Z_DIM) {
        size_t zi = row * Z_DIM + col;
        val = eps[zi] * stdv[zi] + mu[zi];
    } else {
        val = x[row * D_IN + (col - Z_DIM)];
    }
    cat[idx] = tanhf(val);
}

// ---------------------------------------------------------------------------
extern "C" void kernel_launch(void* const* d_in, const int* in_sizes, int n_in,
                              void* d_out, int out_size)
{
    const float* x   = (const float*)d_in[0];
    const float* eps = (const float*)d_in[1];
    const float* W1  = (const float*)d_in[2];
    const float* b1  = (const float*)d_in[3];
    const float* g1  = (const float*)d_in[4];
    const float* be1 = (const float*)d_in[5];
    const float* W2  = (const float*)d_in[6];
    const float* b2  = (const float*)d_in[7];
    const float* g2  = (const float*)d_in[8];
    const float* be2 = (const float*)d_in[9];
    const float* Wmu = (const float*)d_in[10];
    const float* bmu = (const float*)d_in[11];
    const float* Wls = (const float*)d_in[12];
    const float* bls = (const float*)d_in[13];
    const float* Wzw = (const float*)d_in[14];
    const float* bzw = (const float*)d_in[15];

    float* out_p = (float*)d_out;
    float* mu_p  = out_p + MU_OFF;
    float* std_p = out_p + STD_OFF;

    float* c_p;   cudaGetSymbolAddress((void**)&c_p,   g_c);
    float* h_p;   cudaGetSymbolAddress((void**)&h_p,   g_h);
    float* cat_p; cudaGetSymbolAddress((void**)&cat_p, g_cat);

    dim3 blk(256);

    // 1) c = x @ W1^T + b1
    gemm_nt_kernel<<<dim3(Z_DIM / BN, M_TOK / BM), blk>>>(
        x, W1, b1, c_p, M_TOK, Z_DIM, D_IN, 0);
    // 2) h = tanh(LN(c))
    ln_tanh_kernel<<<M_TOK, blk>>>(c_p, g1, be1, h_p);
    // 3) c = h @ W2^T + b2
    gemm_nt_kernel<<<dim3(Z_DIM / BN, M_TOK / BM), blk>>>(
        h_p, W2, b2, c_p, M_TOK, Z_DIM, Z_DIM, 0);
    // 4) h = tanh(LN(c))
    ln_tanh_kernel<<<M_TOK, blk>>>(c_p, g2, be2, h_p);
    // 5) mu = h @ Wmu^T + bmu   (direct to output)
    gemm_nt_kernel<<<dim3(Z_DIM / BN, M_TOK / BM), blk>>>(
        h_p, Wmu, bmu, mu_p, M_TOK, Z_DIM, Z_DIM, 0);
    // 6) std = exp(0.5*(h @ Wls^T + bls))   (direct to output)
    gemm_nt_kernel<<<dim3(Z_DIM / BN, M_TOK / BM), blk>>>(
        h_p, Wls, bls, std_p, M_TOK, Z_DIM, Z_DIM, 1);
    // 7) cat = tanh([eps*std+mu, x])
    {
        size_t total = (size_t)M_TOK * CAT_DIM;
        int grid = (int)((total + 255) / 256);
        build_cat_kernel<<<grid, blk>>>(eps, x, mu_p, std_p, cat_p);
    }
    // 8) out = cat @ Wzw^T + bzw
    gemm_nt_kernel<<<dim3(D_OUT / BN, M_TOK / BM), blk>>>(
        cat_p, Wzw, bzw, out_p, M_TOK, D_OUT, CAT_DIM, 0);
}

// round 2
// speedup vs baseline: 2.9622x; 2.9622x over previous
#include <cuda_runtime.h>
#include <math.h>
#include <stdint.h>

// Problem constants
#define M_TOK   8192      // B*S = 4*2048
#define D_IN    4096
#define Z_DIM   1024
#define D_OUT   4096
#define CAT_DIM 5120      // Z + D_IN
#define LN_EPS  1e-5f

// d_out packing: (out[8192,4096], mu[8192,1024], std[8192,1024])
#define MU_OFF  (M_TOK * (size_t)D_OUT)
#define STD_OFF (MU_OFF + (size_t)M_TOK * Z_DIM)

// Scratch (device globals — allocation-free per harness rules)
__device__ __align__(256) float g_c[(size_t)M_TOK * Z_DIM];
__device__ __align__(256) float g_h[(size_t)M_TOK * Z_DIM];
__device__ __align__(256) float g_cat[(size_t)M_TOK * CAT_DIM];

// ---------------------------------------------------------------------------
// PTX helpers
// ---------------------------------------------------------------------------
__device__ __forceinline__ void cp16(uint32_t dst, const void* src) {
    asm volatile("cp.async.cg.shared.global [%0], [%1], 16;\n" :: "r"(dst), "l"(src));
}
__device__ __forceinline__ void cp_commit() {
    asm volatile("cp.async.commit_group;\n" ::: "memory");
}
__device__ __forceinline__ void cp_wait1() {
    asm volatile("cp.async.wait_group 1;\n" ::: "memory");
}
__device__ __forceinline__ void ldsm4(uint32_t* r, uint32_t addr) {
    asm volatile("ldmatrix.sync.aligned.m8n8.x4.shared.b16 {%0,%1,%2,%3}, [%4];\n"
        : "=r"(r[0]), "=r"(r[1]), "=r"(r[2]), "=r"(r[3]) : "r"(addr));
}
__device__ __forceinline__ uint32_t f2tf(uint32_t x) {
    uint32_t y;
    asm("cvt.rna.tf32.f32 %0, %1;\n" : "=r"(y) : "f"(__uint_as_float(x)));
    return y;
}
__device__ __forceinline__ void mma_tf32(float* d, const uint32_t* a, const uint32_t* b) {
    asm volatile(
        "mma.sync.aligned.m16n8k8.row.col.f32.tf32.tf32.f32 "
        "{%0,%1,%2,%3}, {%4,%5,%6,%7}, {%8,%9}, {%0,%1,%2,%3};\n"
        : "+f"(d[0]), "+f"(d[1]), "+f"(d[2]), "+f"(d[3])
        : "r"(a[0]), "r"(a[1]), "r"(a[2]), "r"(a[3]), "r"(b[0]), "r"(b[1]));
}

// ---------------------------------------------------------------------------
// Tensor-core GEMM: C[M,N] = A[M,K] * B[N,K]^T + bias[N]
// mode 0: plain.  mode 1: C = exp(0.5*(acc+bias)).
// Block tile 128x128, BK=16, 3-stage cp.async, 8 warps (2M x 4N), 64x32/warp.
// smem: per stage A 128x16 + B 128x16 floats = 16KB; 3 stages = 48KB static.
// Swizzle: float (row,col) -> row*16 + ((col>>2 ^ ((row>>1)&3))<<2) + (col&3)
//   => the 8 rows touched by one ldmatrix land in 8 distinct 16B bank groups.
// ---------------------------------------------------------------------------
#define GBK 16
#define STAGE_FLOATS 4096           // 2048 A + 2048 B
#define STAGE_BYTES  16384

__global__ void __launch_bounds__(256)
gemm_tf32_kernel(const float* __restrict__ A, const float* __restrict__ B,
                 const float* __restrict__ bias, float* __restrict__ C,
                 int M, int N, int K, int mode)
{
    __shared__ float smem[3 * STAGE_FLOATS];   // 48 KB exactly

    const int tid  = threadIdx.x;
    const int lane = tid & 31;
    const int warp = tid >> 5;
    const int warp_m = warp & 1;
    const int warp_n = warp >> 1;

    const int bm = blockIdx.y * 128;
    const int bn = blockIdx.x * 128;

    const uint32_t sm_base = (uint32_t)__cvta_generic_to_shared(smem);

    // ---- cp.async mapping: thread -> (row = tid>>1, chunks (tid&1)*2 + {0,1})
    const int ld_row = tid >> 1;
    const int ld_c0  = (tid & 1) * 2;
    const int ld_swz = (ld_row >> 1) & 3;
    const float* Ag = A + (size_t)(bm + ld_row) * K + ld_c0 * 4;
    const float* Bg = B + (size_t)(bn + ld_row) * K + ld_c0 * 4;
    uint32_t a_dst[2], b_dst[2];
#pragma unroll
    for (int i = 0; i < 2; i++) {
        uint32_t off = (uint32_t)(ld_row * 16 + (((ld_c0 + i) ^ ld_swz) << 2)) * 4u;
        a_dst[i] = sm_base + off;
        b_dst[i] = sm_base + 2048u * 4u + off;
    }

    // ---- ldmatrix address precompute
    // A: lane -> subrow sa (0..15), hi chunk bit, swizzle key
    const int sa   = (lane & 7) + ((lane >> 3) & 1) * 8;
    const int hiA  = (lane >> 4) & 1;
    const int aswz = (sa >> 1) & 3;
    uint32_t a_base[4];
#pragma unroll
    for (int mf = 0; mf < 4; mf++)
        a_base[mf] = sm_base + (uint32_t)(warp_m * 64 + mf * 16 + sa) * 64u;

    // B: lane -> n-row within group, hi chunk bit, swizzle key
    const int hiB  = (lane >> 3) & 1;
    const int nbr  = ((lane >> 4) & 1) * 8 + (lane & 7);
    const int bswz = ((lane & 7) >> 1) & 3;
    uint32_t b_base[2];
#pragma unroll
    for (int p = 0; p < 2; p++)
        b_base[p] = sm_base + 2048u * 4u + (uint32_t)(warp_n * 32 + p * 16 + nbr) * 64u;

    // ---- bias preload (per-thread epilogue columns)
    float bias2[4][2];
#pragma unroll
    for (int nf = 0; nf < 4; nf++) {
        int col = bn + warp_n * 32 + nf * 8 + (lane & 3) * 2;
        bias2[nf][0] = __ldg(bias + col);
        bias2[nf][1] = __ldg(bias + col + 1);
    }

    float acc[4][4][4];
#pragma unroll
    for (int mf = 0; mf < 4; mf++)
#pragma unroll
        for (int nf = 0; nf < 4; nf++)
#pragma unroll
            for (int r = 0; r < 4; r++) acc[mf][nf][r] = 0.f;

    const int KT = K / GBK;

    // ---- prologue: prefetch stages 0,1
#pragma unroll
    for (int s = 0; s < 2; s++) {
        if (s < KT) {
            const float* ap = Ag + s * GBK;
            const float* bp = Bg + s * GBK;
            uint32_t so = (uint32_t)s * STAGE_BYTES;
            cp16(a_dst[0] + so, ap);
            cp16(a_dst[1] + so, ap + 4);
            cp16(b_dst[0] + so, bp);
            cp16(b_dst[1] + so, bp + 4);
        }
        cp_commit();
    }

    int s_cur = 0;
    for (int kt = 0; kt < KT; kt++) {
        cp_wait1();
        __syncthreads();

        // prefetch stage kt+2
        {
            int nxt = kt + 2;
            if (nxt < KT) {
                int sn = nxt - (nxt / 3) * 3;
                const float* ap = Ag + nxt * GBK;
                const float* bp = Bg + nxt * GBK;
                uint32_t so = (uint32_t)sn * STAGE_BYTES;
                cp16(a_dst[0] + so, ap);
                cp16(a_dst[1] + so, ap + 4);
                cp16(b_dst[0] + so, bp);
                cp16(b_dst[1] + so, bp + 4);
            }
            cp_commit();
        }

        // compute on stage s_cur
        const uint32_t so = (uint32_t)s_cur * STAGE_BYTES;
#pragma unroll
        for (int kk = 0; kk < 2; kk++) {
            uint32_t a[4][4];
#pragma unroll
            for (int mf = 0; mf < 4; mf++) {
                uint32_t addr = a_base[mf] + so + (uint32_t)(((kk * 2 + hiA) ^ aswz) << 4);
                ldsm4(a[mf], addr);
            }
            uint32_t b[4][2];
#pragma unroll
            for (int p = 0; p < 2; p++) {
                uint32_t r[4];
                uint32_t addr = b_base[p] + so + (uint32_t)(((kk * 2 + hiB) ^ bswz) << 4);
                ldsm4(r, addr);
                b[2 * p][0] = r[0]; b[2 * p][1] = r[1];
                b[2 * p + 1][0] = r[2]; b[2 * p + 1][1] = r[3];
            }
            // round to tf32
#pragma unroll
            for (int mf = 0; mf < 4; mf++)
#pragma unroll
                for (int r = 0; r < 4; r++) a[mf][r] = f2tf(a[mf][r]);
#pragma unroll
            for (int nf = 0; nf < 4; nf++) {
                b[nf][0] = f2tf(b[nf][0]);
                b[nf][1] = f2tf(b[nf][1]);
            }
#pragma unroll
            for (int mf = 0; mf < 4; mf++)
#pragma unroll
                for (int nf = 0; nf < 4; nf++)
                    mma_tf32(acc[mf][nf], a[mf], b[nf]);
        }

        s_cur++; if (s_cur == 3) s_cur = 0;
        __syncthreads();
    }

    // ---- epilogue
#pragma unroll
    for (int mf = 0; mf < 4; mf++) {
        int r0 = bm + warp_m * 64 + mf * 16 + (lane >> 2);
#pragma unroll
        for (int nf = 0; nf < 4; nf++) {
            int col = bn + warp_n * 32 + nf * 8 + (lane & 3) * 2;
            float v0 = acc[mf][nf][0] + bias2[nf][0];
            float v1 = acc[mf][nf][1] + bias2[nf][1];
            float v2 = acc[mf][nf][2] + bias2[nf][0];
            float v3 = acc[mf][nf][3] + bias2[nf][1];
            if (mode == 1) {
                v0 = expf(0.5f * v0); v1 = expf(0.5f * v1);
                v2 = expf(0.5f * v2); v3 = expf(0.5f * v3);
            }
            float2 w0 = make_float2(v0, v1);
            float2 w1 = make_float2(v2, v3);
            *(float2*)(C + (size_t)r0 * N + col) = w0;
            *(float2*)(C + (size_t)(r0 + 8) * N + col) = w1;
        }
    }
}

// ---------------------------------------------------------------------------
// LayerNorm (over 1024) + tanh. One block per row, 256 threads x 4 elems.
// ---------------------------------------------------------------------------
__global__ void __launch_bounds__(256)
ln_tanh_kernel(const float* __restrict__ in, const float* __restrict__ gamma,
               const float* __restrict__ beta, float* __restrict__ out)
{
    const int row = blockIdx.x;
    const int tid = threadIdx.x;
    const float* p = in + (size_t)row * Z_DIM;

    float4 v = *(const float4*)(p + tid * 4);

    __shared__ float red[8];
    float s = v.x + v.y + v.z + v.w;
#pragma unroll
    for (int o = 16; o > 0; o >>= 1) s += __shfl_down_sync(0xffffffffu, s, o);
    if ((tid & 31) == 0) red[tid >> 5] = s;
    __syncthreads();
    {
        float t = (tid < 8) ? red[tid] : 0.f;
#pragma unroll
        for (int o = 4; o > 0; o >>= 1) t += __shfl_down_sync(0xffu, t, o);
        if (tid == 0) red[0] = t;
    }
    __syncthreads();
    const float mean = red[0] * (1.0f / Z_DIM);
    __syncthreads();

    float d0 = v.x - mean, d1 = v.y - mean, d2 = v.z - mean, d3 = v.w - mean;
    float s2 = d0 * d0 + d1 * d1 + d2 * d2 + d3 * d3;
#pragma unroll
    for (int o = 16; o > 0; o >>= 1) s2 += __shfl_down_sync(0xffffffffu, s2, o);
    if ((tid & 31) == 0) red[tid >> 5] = s2;
    __syncthreads();
    {
        float t = (tid < 8) ? red[tid] : 0.f;
#pragma unroll
        for (int o = 4; o > 0; o >>= 1) t += __shfl_down_sync(0xffu, t, o);
        if (tid == 0) red[0] = t;
    }
    __syncthreads();
    const float rstd = rsqrtf(red[0] * (1.0f / Z_DIM) + LN_EPS);

    const int col = tid * 4;
    float4 g = *(const float4*)(gamma + col);
    float4 b = *(const float4*)(beta + col);
    float4 o;
    o.x = tanhf(d0 * rstd * g.x + b.x);
    o.y = tanhf(d1 * rstd * g.y + b.y);
    o.z = tanhf(d2 * rstd * g.z + b.z);
    o.w = tanhf(d3 * rstd * g.w + b.w);
    *(float4*)(out + (size_t)row * Z_DIM + col) = o;
}

// ---------------------------------------------------------------------------
// Build tanh(concat(z, x)):  z = eps*std + mu
// ---------------------------------------------------------------------------
__global__ void __launch_bounds__(256)
build_cat_kernel(const float* __restrict__ eps, const float* __restrict__ x,
                 const float* __restrict__ mu, const float* __restrict__ stdv,
                 float* __restrict__ cat)
{
    size_t idx = (size_t)blockIdx.x * blockDim.x + threadIdx.x;
    size_t total = (size_t)M_TOK * CAT_DIM;
    if (idx >= total) return;
    size_t row = idx / CAT_DIM;
    int col = (int)(idx - row * CAT_DIM);
    float val;
    if (col < Z_DIM) {
        size_t zi = row * Z_DIM + col;
        val = eps[zi] * stdv[zi] + mu[zi];
    } else {
        val = x[row * D_IN + (col - Z_DIM)];
    }
    cat[idx] = tanhf(val);
}

// ---------------------------------------------------------------------------
extern "C" void kernel_launch(void* const* d_in, const int* in_sizes, int n_in,
                              void* d_out, int out_size)
{
    const float* x   = (const float*)d_in[0];
    const float* eps = (const float*)d_in[1];
    const float* W1  = (const float*)d_in[2];
    const float* b1  = (const float*)d_in[3];
    const float* g1  = (const float*)d_in[4];
    const float* be1 = (const float*)d_in[5];
    const float* W2  = (const float*)d_in[6];
    const float* b2  = (const float*)d_in[7];
    const float* g2  = (const float*)d_in[8];
    const float* be2 = (const float*)d_in[9];
    const float* Wmu = (const float*)d_in[10];
    const float* bmu = (const float*)d_in[11];
    const float* Wls = (const float*)d_in[12];
    const float* bls = (const float*)d_in[13];
    const float* Wzw = (const float*)d_in[14];
    const float* bzw = (const float*)d_in[15];

    float* out_p = (float*)d_out;
    float* mu_p  = out_p + MU_OFF;
    float* std_p = out_p + STD_OFF;

    float* c_p;   cudaGetSymbolAddress((void**)&c_p,   g_c);
    float* h_p;   cudaGetSymbolAddress((void**)&h_p,   g_h);
    float* cat_p; cudaGetSymbolAddress((void**)&cat_p, g_cat);

    dim3 blk(256);

    // 1) c = x @ W1^T + b1
    gemm_tf32_kernel<<<dim3(Z_DIM / 128, M_TOK / 128), blk>>>(
        x, W1, b1, c_p, M_TOK, Z_DIM, D_IN, 0);
    // 2) h = tanh(LN(c))
    ln_tanh_kernel<<<M_TOK, blk>>>(c_p, g1, be1, h_p);
    // 3) c = h @ W2^T + b2
    gemm_tf32_kernel<<<dim3(Z_DIM / 128, M_TOK / 128), blk>>>(
        h_p, W2, b2, c_p, M_TOK, Z_DIM, Z_DIM, 0);
    // 4) h = tanh(LN(c))
    ln_tanh_kernel<<<M_TOK, blk>>>(c_p, g2, be2, h_p);
    // 5) mu = h @ Wmu^T + bmu
    gemm_tf32_kernel<<<dim3(Z_DIM / 128, M_TOK / 128), blk>>>(
        h_p, Wmu, bmu, mu_p, M_TOK, Z_DIM, Z_DIM, 0);
    // 6) std = exp(0.5*(h @ Wls^T + bls))
    gemm_tf32_kernel<<<dim3(Z_DIM / 128, M_TOK / 128), blk>>>(
        h_p, Wls, bls, std_p, M_TOK, Z_DIM, Z_DIM, 1);
    // 7) cat = tanh([eps*std+mu, x])
    {
        size_t total = (size_t)M_TOK * CAT_DIM;
        int grid = (int)((total + 255) / 256);
        build_cat_kernel<<<grid, blk>>>(eps, x, mu_p, std_p, cat_p);
    }
    // 8) out = cat @ Wzw^T + bzw
    gemm_tf32_kernel<<<dim3(D_OUT / 128, M_TOK / 128), blk>>>(
        cat_p, Wzw, bzw, out_p, M_TOK, D_OUT, CAT_DIM, 0);
}

// round 4
// speedup vs baseline: 3.0533x; 1.0307x over previous
#include <cuda_runtime.h>
#include <math.h>
#include <stdint.h>

// Problem constants
#define M_TOK   8192
#define D_IN    4096
#define Z_DIM   1024
#define D_OUT   4096
#define CAT_DIM 5120
#define LN_EPS  1e-5f

#define MU_OFF  (M_TOK * (size_t)D_OUT)
#define STD_OFF (MU_OFF + (size_t)M_TOK * Z_DIM)

// Scratch (device globals — allocation-free per harness rules)
__device__ __align__(256) float g_c[(size_t)M_TOK * Z_DIM];
__device__ __align__(256) float g_h[(size_t)M_TOK * Z_DIM];
__device__ __align__(256) float g_cat[(size_t)M_TOK * CAT_DIM];
__device__ __align__(256) float g_x32[(size_t)M_TOK * D_IN];
// Rounded weights, packed: W1 | W2 | Wmu | Wls | Wzw  (Wmu,Wls adjacent => fused GEMM)
#define W1_OFF  0
#define W2_OFF  4194304
#define WMU_OFF 5242880
#define WLS_OFF 6291456
#define WZW_OFF 7340032
#define W_TOTAL 28311552
__device__ __align__(256) float g_w[(size_t)W_TOTAL];

// ---------------------------------------------------------------------------
// PTX helpers
// ---------------------------------------------------------------------------
__device__ __forceinline__ void cp16(uint32_t dst, const void* src) {
    asm volatile("cp.async.cg.shared.global [%0], [%1], 16;\n" :: "r"(dst), "l"(src));
}
__device__ __forceinline__ void cp_commit() {
    asm volatile("cp.async.commit_group;\n" ::: "memory");
}
__device__ __forceinline__ void cp_wait1() {
    asm volatile("cp.async.wait_group 1;\n" ::: "memory");
}
__device__ __forceinline__ void ldsm4(uint32_t* r, uint32_t addr) {
    asm volatile("ldmatrix.sync.aligned.m8n8.x4.shared.b16 {%0,%1,%2,%3}, [%4];\n"
        : "=r"(r[0]), "=r"(r[1]), "=r"(r[2]), "=r"(r[3]) : "r"(addr));
}
__device__ __forceinline__ float rtf(float x) {
    uint32_t y;
    asm("cvt.rna.tf32.f32 %0, %1;\n" : "=r"(y) : "f"(x));
    return __uint_as_float(y);
}
__device__ __forceinline__ void mma_tf32(float* d, const uint32_t* a, const uint32_t* b) {
    asm volatile(
        "mma.sync.aligned.m16n8k8.row.col.f32.tf32.tf32.f32 "
        "{%0,%1,%2,%3}, {%4,%5,%6,%7}, {%8,%9}, {%0,%1,%2,%3};\n"
        : "+f"(d[0]), "+f"(d[1]), "+f"(d[2]), "+f"(d[3])
        : "r"(a[0]), "r"(a[1]), "r"(a[2]), "r"(a[3]), "r"(b[0]), "r"(b[1]));
}

// ---------------------------------------------------------------------------
// Tensor-core GEMM: C[M,N] = A[M,K] * B[N,K]^T + bias[N]
// Operands must be PRE-ROUNDED to tf32 (rna) — no cvt in the hot loop; mma
// truncation of pre-rounded values == rna rounding.
// mode 0: plain epilogue to C (stride N).
// mode 2: split epilogue — block-columns < Z_DIM go to C (stride Z_DIM, +biasA),
//         block-columns >= Z_DIM go to exp(0.5*(v+biasB)) into C2 (stride Z_DIM).
// Block tile 128x128, BK=16, 3-stage cp.async, 8 warps (2M x 4N), 64x32/warp.
// ---------------------------------------------------------------------------
#define GBK 16
#define STAGE_FLOATS 4096           // 2048 A + 2048 B
#define STAGE_BYTES  16384

__global__ void __launch_bounds__(256)
gemm_tf32_kernel(const float* __restrict__ A, const float* __restrict__ B,
                 const float* __restrict__ biasA, const float* __restrict__ biasB,
                 float* __restrict__ C, float* __restrict__ C2,
                 int M, int N, int K, int mode)
{
    __shared__ float smem[3 * STAGE_FLOATS];   // 48 KB

    const int tid  = threadIdx.x;
    const int lane = tid & 31;
    const int warp = tid >> 5;
    const int warp_m = warp & 1;
    const int warp_n = warp >> 1;

    const int bm = blockIdx.y * 128;
    const int bn = blockIdx.x * 128;

    const uint32_t sm_base = (uint32_t)__cvta_generic_to_shared(smem);

    // ---- cp.async mapping
    const int ld_row = tid >> 1;
    const int ld_c0  = (tid & 1) * 2;
    const int ld_swz = (ld_row >> 1) & 3;
    const float* Ag = A + (size_t)(bm + ld_row) * K + ld_c0 * 4;
    const float* Bg = B + (size_t)(bn + ld_row) * K + ld_c0 * 4;
    uint32_t a_dst[2], b_dst[2];
#pragma unroll
    for (int i = 0; i < 2; i++) {
        uint32_t off = (uint32_t)(ld_row * 16 + (((ld_c0 + i) ^ ld_swz) << 2)) * 4u;
        a_dst[i] = sm_base + off;
        b_dst[i] = sm_base + 2048u * 4u + off;
    }

    // ---- ldmatrix address precompute
    const int sa   = (lane & 7) + ((lane >> 3) & 1) * 8;
    const int hiA  = (lane >> 4) & 1;
    const int aswz = (sa >> 1) & 3;
    uint32_t a_base[4];
#pragma unroll
    for (int mf = 0; mf < 4; mf++)
        a_base[mf] = sm_base + (uint32_t)(warp_m * 64 + mf * 16 + sa) * 64u;

    const int hiB  = (lane >> 3) & 1;
    const int nbr  = ((lane >> 4) & 1) * 8 + (lane & 7);
    const int bswz = ((lane & 7) >> 1) & 3;
    uint32_t b_base[2];
#pragma unroll
    for (int p = 0; p < 2; p++)
        b_base[p] = sm_base + 2048u * 4u + (uint32_t)(warp_n * 32 + p * 16 + nbr) * 64u;

    // ---- epilogue routing (resolved per block; halves are 128-aligned)
    const float* bp = biasA;
    float* Cp = C;
    int cadj = 0, effN = N, emode = 0;
    if (mode == 2) {
        effN = Z_DIM;
        if (bn >= Z_DIM) { bp = biasB; Cp = C2; cadj = Z_DIM; emode = 1; }
    }

    float bias2[4][2];
#pragma unroll
    for (int nf = 0; nf < 4; nf++) {
        int col = bn - cadj + warp_n * 32 + nf * 8 + (lane & 3) * 2;
        bias2[nf][0] = __ldg(bp + col);
        bias2[nf][1] = __ldg(bp + col + 1);
    }

    float acc[4][4][4];
#pragma unroll
    for (int mf = 0; mf < 4; mf++)
#pragma unroll
        for (int nf = 0; nf < 4; nf++)
#pragma unroll
            for (int r = 0; r < 4; r++) acc[mf][nf][r] = 0.f;

    const int KT = K / GBK;

    // ---- prologue: prefetch stages 0,1
#pragma unroll
    for (int s = 0; s < 2; s++) {
        if (s < KT) {
            const float* ap = Ag + s * GBK;
            const float* bpq = Bg + s * GBK;
            uint32_t so = (uint32_t)s * STAGE_BYTES;
            cp16(a_dst[0] + so, ap);
            cp16(a_dst[1] + so, ap + 4);
            cp16(b_dst[0] + so, bpq);
            cp16(b_dst[1] + so, bpq + 4);
        }
        cp_commit();
    }

    int s_cur = 0;
    for (int kt = 0; kt < KT; kt++) {
        cp_wait1();
        __syncthreads();

        {
            int nxt = kt + 2;
            if (nxt < KT) {
                int sn = nxt - (nxt / 3) * 3;
                const float* ap = Ag + nxt * GBK;
                const float* bpq = Bg + nxt * GBK;
                uint32_t so = (uint32_t)sn * STAGE_BYTES;
                cp16(a_dst[0] + so, ap);
                cp16(a_dst[1] + so, ap + 4);
                cp16(b_dst[0] + so, bpq);
                cp16(b_dst[1] + so, bpq + 4);
            }
            cp_commit();
        }

        const uint32_t so = (uint32_t)s_cur * STAGE_BYTES;
#pragma unroll
        for (int kk = 0; kk < 2; kk++) {
            uint32_t a[4][4];
#pragma unroll
            for (int mf = 0; mf < 4; mf++) {
                uint32_t addr = a_base[mf] + so + (uint32_t)(((kk * 2 + hiA) ^ aswz) << 4);
                ldsm4(a[mf], addr);
            }
            uint32_t b[4][2];
#pragma unroll
            for (int p = 0; p < 2; p++) {
                uint32_t r[4];
                uint32_t addr = b_base[p] + so + (uint32_t)(((kk * 2 + hiB) ^ bswz) << 4);
                ldsm4(r, addr);
                b[2 * p][0] = r[0]; b[2 * p][1] = r[1];
                b[2 * p + 1][0] = r[2]; b[2 * p + 1][1] = r[3];
            }
            // inputs pre-rounded to tf32 — no cvt here
#pragma unroll
            for (int mf = 0; mf < 4; mf++)
#pragma unroll
                for (int nf = 0; nf < 4; nf++)
                    mma_tf32(acc[mf][nf], a[mf], b[nf]);
        }

        s_cur++; if (s_cur == 3) s_cur = 0;
        __syncthreads();
    }

    // ---- epilogue
#pragma unroll
    for (int mf = 0; mf < 4; mf++) {
        int r0 = bm + warp_m * 64 + mf * 16 + (lane >> 2);
#pragma unroll
        for (int nf = 0; nf < 4; nf++) {
            int col = bn - cadj + warp_n * 32 + nf * 8 + (lane & 3) * 2;
            float v0 = acc[mf][nf][0] + bias2[nf][0];
            float v1 = acc[mf][nf][1] + bias2[nf][1];
            float v2 = acc[mf][nf][2] + bias2[nf][0];
            float v3 = acc[mf][nf][3] + bias2[nf][1];
            if (emode == 1) {
                v0 = expf(0.5f * v0); v1 = expf(0.5f * v1);
                v2 = expf(0.5f * v2); v3 = expf(0.5f * v3);
            }
            *(float2*)(Cp + (size_t)r0 * effN + col) = make_float2(v0, v1);
            *(float2*)(Cp + (size_t)(r0 + 8) * effN + col) = make_float2(v2, v3);
        }
    }
}

// ---------------------------------------------------------------------------
// Round fp32 -> tf32 (rna), vectorized
// ---------------------------------------------------------------------------
__global__ void __launch_bounds__(256)
round_tf32_kernel(const float* __restrict__ in, float* __restrict__ out, size_t n4)
{
    size_t i = (size_t)blockIdx.x * blockDim.x + threadIdx.x;
    if (i >= n4) return;
    float4 v = *(const float4*)(in + i * 4);
    v.x = rtf(v.x); v.y = rtf(v.y); v.z = rtf(v.z); v.w = rtf(v.w);
    *(float4*)(out + i * 4) = v;
}

// ---------------------------------------------------------------------------
// LayerNorm (1024) + tanh, output rounded to tf32 (feeds next GEMM).
// ---------------------------------------------------------------------------
__global__ void __launch_bounds__(256)
ln_tanh_kernel(const float* __restrict__ in, const float* __restrict__ gamma,
               const float* __restrict__ beta, float* __restrict__ out)
{
    const int row = blockIdx.x;
    const int tid = threadIdx.x;
    const float* p = in + (size_t)row * Z_DIM;

    float4 v = *(const float4*)(p + tid * 4);

    __shared__ float red[8];
    float s = v.x + v.y + v.z + v.w;
#pragma unroll
    for (int o = 16; o > 0; o >>= 1) s += __shfl_down_sync(0xffffffffu, s, o);
    if ((tid & 31) == 0) red[tid >> 5] = s;
    __syncthreads();
    {
        float t = (tid < 8) ? red[tid] : 0.f;
#pragma unroll
        for (int o = 4; o > 0; o >>= 1) t += __shfl_down_sync(0xffu, t, o);
        if (tid == 0) red[0] = t;
    }
    __syncthreads();
    const float mean = red[0] * (1.0f / Z_DIM);
    __syncthreads();

    float d0 = v.x - mean, d1 = v.y - mean, d2 = v.z - mean, d3 = v.w - mean;
    float s2 = d0 * d0 + d1 * d1 + d2 * d2 + d3 * d3;
#pragma unroll
    for (int o = 16; o > 0; o >>= 1) s2 += __shfl_down_sync(0xffffffffu, s2, o);
    if ((tid & 31) == 0) red[tid >> 5] = s2;
    __syncthreads();
    {
        float t = (tid < 8) ? red[tid] : 0.f;
#pragma unroll
        for (int o = 4; o > 0; o >>= 1) t += __shfl_down_sync(0xffu, t, o);
        if (tid == 0) red[0] = t;
    }
    __syncthreads();
    const float rstd = rsqrtf(red[0] * (1.0f / Z_DIM) + LN_EPS);

    const int col = tid * 4;
    float4 g = *(const float4*)(gamma + col);
    float4 b = *(const float4*)(beta + col);
    float4 o;
    o.x = rtf(tanhf(d0 * rstd * g.x + b.x));
    o.y = rtf(tanhf(d1 * rstd * g.y + b.y));
    o.z = rtf(tanhf(d2 * rstd * g.z + b.z));
    o.w = rtf(tanhf(d3 * rstd * g.w + b.w));
    *(float4*)(out + (size_t)row * Z_DIM + col) = o;
}

// ---------------------------------------------------------------------------
// cat = tf32_round(tanh([eps*std+mu, x]))
// ---------------------------------------------------------------------------
__global__ void __launch_bounds__(256)
build_cat_kernel(const float* __restrict__ eps, const float* __restrict__ x,
                 const float* __restrict__ mu, const float* __restrict__ stdv,
                 float* __restrict__ cat)
{
    size_t idx = (size_t)blockIdx.x * blockDim.x + threadIdx.x;
    size_t total = (size_t)M_TOK * CAT_DIM;
    if (idx >= total) return;
    size_t row = idx / CAT_DIM;
    int col = (int)(idx - row * CAT_DIM);
    float val;
    if (col < Z_DIM) {
        size_t zi = row * Z_DIM + col;
        val = eps[zi] * stdv[zi] + mu[zi];
    } else {
        val = x[row * D_IN + (col - Z_DIM)];
    }
    cat[idx] = rtf(tanhf(val));
}

// ---------------------------------------------------------------------------
extern "C" void kernel_launch(void* const* d_in, const int* in_sizes, int n_in,
                              void* d_out, int out_size)
{
    const float* x   = (const float*)d_in[0];
    const float* eps = (const float*)d_in[1];
    const float* W1  = (const float*)d_in[2];
    const float* b1  = (const float*)d_in[3];
    const float* g1  = (const float*)d_in[4];
    const float* be1 = (const float*)d_in[5];
    const float* W2  = (const float*)d_in[6];
    const float* b2  = (const float*)d_in[7];
    const float* g2  = (const float*)d_in[8];
    const float* be2 = (const float*)d_in[9];
    const float* Wmu = (const float*)d_in[10];
    const float* bmu = (const float*)d_in[11];
    const float* Wls = (const float*)d_in[12];
    const float* bls = (const float*)d_in[13];
    const float* Wzw = (const float*)d_in[14];
    const float* bzw = (const float*)d_in[15];

    float* out_p = (float*)d_out;
    float* mu_p  = out_p + MU_OFF;
    float* std_p = out_p + STD_OFF;

    float* c_p;   cudaGetSymbolAddress((void**)&c_p,   g_c);
    float* h_p;   cudaGetSymbolAddress((void**)&h_p,   g_h);
    float* cat_p; cudaGetSymbolAddress((void**)&cat_p, g_cat);
    float* x32_p; cudaGetSymbolAddress((void**)&x32_p, g_x32);
    float* w_p;   cudaGetSymbolAddress((void**)&w_p,   g_w);

    dim3 blk(256);

    // 0) pre-round all GEMM operands to tf32 (rna)
    {
        auto rnd = [&](const float* in, float* out, size_t n) {
            size_t n4 = n / 4;
            round_tf32_kernel<<<(unsigned)((n4 + 255) / 256), blk>>>(in, out, n4);
        };
        rnd(x,   x32_p,         (size_t)M_TOK * D_IN);
        rnd(W1,  w_p + W1_OFF,  (size_t)Z_DIM * D_IN);
        rnd(W2,  w_p + W2_OFF,  (size_t)Z_DIM * Z_DIM);
        rnd(Wmu, w_p + WMU_OFF, (size_t)Z_DIM * Z_DIM);
        rnd(Wls, w_p + WLS_OFF, (size_t)Z_DIM * Z_DIM);
        rnd(Wzw, w_p + WZW_OFF, (size_t)D_OUT * CAT_DIM);
    }

    // 1) c = x @ W1^T + b1
    gemm_tf32_kernel<<<dim3(Z_DIM / 128, M_TOK / 128), blk>>>(
        x32_p, w_p + W1_OFF, b1, nullptr, c_p, nullptr, M_TOK, Z_DIM, D_IN, 0);
    // 2) h = tanh(LN(c))
    ln_tanh_kernel<<<M_TOK, blk>>>(c_p, g1, be1, h_p);
    // 3) c = h @ W2^T + b2
    gemm_tf32_kernel<<<dim3(Z_DIM / 128, M_TOK / 128), blk>>>(
        h_p, w_p + W2_OFF, b2, nullptr, c_p, nullptr, M_TOK, Z_DIM, Z_DIM, 0);
    // 4) h = tanh(LN(c))
    ln_tanh_kernel<<<M_TOK, blk>>>(c_p, g2, be2, h_p);
    // 5+6) fused: [mu | std] = h @ [Wmu|Wls]^T  (std half gets exp(0.5*..))
    gemm_tf32_kernel<<<dim3(2 * Z_DIM / 128, M_TOK / 128), blk>>>(
        h_p, w_p + WMU_OFF, bmu, bls, mu_p, std_p, M_TOK, 2 * Z_DIM, Z_DIM, 2);
    // 7) cat = tf32(tanh([eps*std+mu, x]))
    {
        size_t total = (size_t)M_TOK * CAT_DIM;
        build_cat_kernel<<<(unsigned)((total + 255) / 256), blk>>>(eps, x, mu_p, std_p, cat_p);
    }
    // 8) out = cat @ Wzw^T + bzw
    gemm_tf32_kernel<<<dim3(D_OUT / 128, M_TOK / 128), blk>>>(
        cat_p, w_p + WZW_OFF, bzw, nullptr, out_p, nullptr, M_TOK, D_OUT, CAT_DIM, 0);
}